// round 13
// baseline (speedup 1.0000x reference)
#include <cuda_runtime.h>
#include <cuda_bf16.h>
#include <math.h>
#include <stdint.h>

// Problem dims (fixed)
#define TT 512
#define BB 512
#define DD 512
#define HH 512
#define BH (BB * HH)  // 262144

// -------------------- device scratch (no allocations allowed) --------------
__device__ float          g_xp[(size_t)TT * BH];            // 512 MB
__device__ __nv_bfloat16  g_wih_h[HH * DD], g_wih_l[HH * DD];
__device__ __nv_bfloat16  g_whh_h[HH * HH], g_whh_l[HH * HH];
__device__ __nv_bfloat16  g_hhi[2][BH], g_hlo[2][BH];

// producer flags: flag[rg][n*32], rg = 0..31 (16-row groups), n = 0..7.
// Monotonic; every owner increments exactly 511 times per launch.
__device__ unsigned g_flag[32][8 * 32];

// -------------------- PTX helpers (sm_80-level only; no 'a' features) ------
__device__ __forceinline__ uint32_t smem_u32(const void* p) {
    uint32_t a;
    asm("{ .reg .u64 t; cvta.to.shared.u64 t, %1; cvt.u32.u64 %0, t; }" : "=r"(a) : "l"(p));
    return a;
}
__device__ __forceinline__ void cp16(uint32_t s, const void* g) {
    asm volatile("cp.async.cg.shared.global [%0], [%1], 16;" :: "r"(s), "l"(g));
}
#define CP_COMMIT() asm volatile("cp.async.commit_group;" ::: "memory")
#define CP_WAIT(n)  asm volatile("cp.async.wait_group %0;" :: "n"(n) : "memory")
#define BARH(id)    asm volatile("bar.sync %0, 128;" :: "r"(id) : "memory")

__device__ __forceinline__ void st_rel_shared(uint32_t addr, unsigned v) {
    asm volatile("st.release.cta.shared.u32 [%0], %1;" :: "r"(addr), "r"(v) : "memory");
}
__device__ __forceinline__ unsigned ld_acq_shared(uint32_t addr) {
    unsigned v;
    asm volatile("ld.acquire.cta.shared.u32 %0, [%1];" : "=r"(v) : "r"(addr) : "memory");
    return v;
}

__device__ __forceinline__ void ldsm4(uint32_t* r, uint32_t addr) {
    asm volatile("ldmatrix.sync.aligned.m8n8.x4.shared.b16 {%0,%1,%2,%3}, [%4];"
                 : "=r"(r[0]), "=r"(r[1]), "=r"(r[2]), "=r"(r[3]) : "r"(addr));
}
__device__ __forceinline__ void mma16816(float* d, const uint32_t* a, uint32_t b0, uint32_t b1) {
    asm volatile("mma.sync.aligned.m16n8k16.row.col.f32.bf16.bf16.f32 "
                 "{%0,%1,%2,%3}, {%4,%5,%6,%7}, {%8,%9}, {%0,%1,%2,%3};"
                 : "+f"(d[0]), "+f"(d[1]), "+f"(d[2]), "+f"(d[3])
                 : "r"(a[0]), "r"(a[1]), "r"(a[2]), "r"(a[3]), "r"(b0), "r"(b1));
}

// fast tanh: 1 - 2/(e^{2x}+1) via MUFU (abs err ~1e-6; saturates correctly)
__device__ __forceinline__ float fast_tanh(float x) {
    float e = __expf(2.0f * x);
    return 1.0f - __fdividef(2.0f, e + 1.0f);
}

// -------------------- split helpers ----------------------------------------
__device__ __forceinline__ void split1(float x, __nv_bfloat16& h, __nv_bfloat16& l) {
    h = __float2bfloat16_rn(x);
    l = __float2bfloat16_rn(x - __bfloat162float(h));
}

__global__ __launch_bounds__(256) void split_kernel(const float* __restrict__ src,
                                                    __nv_bfloat16* __restrict__ hi,
                                                    __nv_bfloat16* __restrict__ lo, int n4) {
    for (int i = blockIdx.x * blockDim.x + threadIdx.x; i < n4; i += gridDim.x * blockDim.x) {
        float4 v = ((const float4*)src)[i];
        __nv_bfloat16 h0, h1, h2, h3, l0, l1, l2, l3;
        split1(v.x, h0, l0); split1(v.y, h1, l1);
        split1(v.z, h2, l2); split1(v.w, h3, l3);
        __nv_bfloat162* ph = (__nv_bfloat162*)hi;
        __nv_bfloat162* pl = (__nv_bfloat162*)lo;
        ph[i * 2] = __nv_bfloat162(h0, h1); ph[i * 2 + 1] = __nv_bfloat162(h2, h3);
        pl[i * 2] = __nv_bfloat162(l0, l1); pl[i * 2 + 1] = __nv_bfloat162(l2, l3);
    }
}

// -------------------- async tile loader (64-col bf16 tiles) ----------------
template <int ROWS, int THREADS>
__device__ __forceinline__ void load_tile_async(const __nv_bfloat16* __restrict__ g,
                                                size_t row0, int kbase,
                                                uint32_t sdst, int tid) {
    constexpr int TOT = ROWS * 8;  // 16B granules
#pragma unroll
    for (int i = 0; i < TOT / THREADS; ++i) {
        int v = i * THREADS + tid;
        int row = v >> 3, g16 = v & 7;
        uint32_t off = (uint32_t)(row * 128 + ((g16 * 16) ^ ((row & 7) * 16)));
        cp16(sdst + off, g + (row0 + (size_t)row) * HH + kbase + g16 * 8);
    }
}

// -------------------- xp GEMM with fused X fp32->hi/lo conversion ----------
// xp[M, N] = X[M,K](fp32) @ (Wih hi/lo)[N,K]^T + bih + bhh; K=512, BK=64.
// BM=64, BN=128, 256 threads, 2 CTAs/SM. B double-buffered via cp.async;
// X loaded fp32 via LDG one chunk ahead, split to bf16 hi/lo in registers,
// stored into the swizzled A tiles (bit-identical to split_kernel + load).
#define FX_SA 8192                       // 64x128B per A split
#define FX_SB 16384                      // 128x128B per B split
#define FX_STAGE (2 * FX_SA + 2 * FX_SB) // 49152
#define FX_SMEM (2 * FX_STAGE)           // 98304

__device__ __forceinline__ void fx_sts_x4(char* smem, uint32_t stageOff, int idx,
                                          const float4& f) {
    int row = idx >> 4, c16 = idx & 15;   // 16 float4 per 64-col row
    __nv_bfloat16 h0, l0, h1, l1, h2, l2, h3, l3;
    split1(f.x, h0, l0); split1(f.y, h1, l1);
    split1(f.z, h2, l2); split1(f.w, h3, l3);
    __nv_bfloat162 hp0(h0, h1), hp1(h2, h3), lp0(l0, l1), lp1(l2, l3);
    uint32_t sw = (uint32_t)(row * 128)
                + (((uint32_t)(c16 >> 1) * 16) ^ ((uint32_t)(row & 7) * 16))
                + (uint32_t)((c16 & 1) * 8);
    *(uint2*)(smem + stageOff + sw) = make_uint2(*(uint32_t*)&hp0, *(uint32_t*)&hp1);
    *(uint2*)(smem + stageOff + FX_SA + sw) = make_uint2(*(uint32_t*)&lp0, *(uint32_t*)&lp1);
}

__global__ void __launch_bounds__(256, 2)
xp_gemm_fx(const float* __restrict__ X,
           const __nv_bfloat16* __restrict__ Bhi, const __nv_bfloat16* __restrict__ Blo,
           const float* __restrict__ bih, const float* __restrict__ bhh,
           float* __restrict__ out_f)
{
    extern __shared__ char smem[];
    const uint32_t sbase = smem_u32(smem);
    const int tid = threadIdx.x;
    const int wid = tid >> 5, lane = tid & 31;
    const size_t bm = (size_t)blockIdx.y * 64;
    const int bn = blockIdx.x * 128;
    const int wm = (wid & 1) * 32;          // BM/WM = 2
    const int wn = (wid >> 1) * 32;         // BN/WN = 4

    float acc[2][4][4];
#pragma unroll
    for (int mi = 0; mi < 2; ++mi)
#pragma unroll
        for (int ni = 0; ni < 4; ++ni)
#pragma unroll
            for (int q = 0; q < 4; ++q) acc[mi][ni][q] = 0.0f;

    const int sub = lane >> 3, li = lane & 7;
    const int arow = (sub & 1) * 8 + li;
    const int akb  = (sub >> 1) * 16;
    const int brow = (sub >> 1) * 8 + li;
    const int bkb  = (sub & 1) * 16;
    const uint32_t swx = (uint32_t)(li * 16);

    // X prefetch registers: 16 floats/thread (4 float4), rows tid>>4 pattern
    const int xrow = tid >> 4;               // base row (idx = i*256+tid -> row = idx>>4)
    float4 xr[4];

    auto ldg_x = [&](int c) {
        const int kb = c * 64;
#pragma unroll
        for (int i = 0; i < 4; ++i) {
            int idx = i * 256 + tid;
            int row = idx >> 4, c16 = idx & 15;
            xr[i] = *(const float4*)(X + (bm + (size_t)row) * DD + kb + c16 * 4);
        }
        (void)xrow;
    };
    auto sts_x = [&](int s) {
        const uint32_t so = (uint32_t)(s * FX_STAGE);
#pragma unroll
        for (int i = 0; i < 4; ++i)
            fx_sts_x4(smem, so, i * 256 + tid, xr[i]);
    };
    auto issue_b = [&](int c, int s) {
        const uint32_t st = sbase + (uint32_t)(s * FX_STAGE);
        const int kb = c * 64;
        load_tile_async<128, 256>(Bhi, (size_t)bn, kb, st + 2 * FX_SA, tid);
        load_tile_async<128, 256>(Blo, (size_t)bn, kb, st + 2 * FX_SA + FX_SB, tid);
        CP_COMMIT();
    };

    // prologue
    ldg_x(0);
    issue_b(0, 0);
    sts_x(0);
    ldg_x(1);

    for (int c = 0; c < 8; ++c) {
        const int s = c & 1;
        if (c + 1 < 8) {
            issue_b(c + 1, s ^ 1);   // target stage freed by S2(c-1)
            CP_WAIT(1);
        } else {
            CP_WAIT(0);
        }
        __syncthreads();             // S1: B(c)+X(c) visible in stage s

        if (c + 1 < 8) sts_x(s ^ 1); // X(c+1) regs -> stage s^1 (freed by S2(c-1))
        if (c + 2 < 8) ldg_x(c + 2); // prefetch, hidden under compute

        const uint32_t st = sbase + (uint32_t)(s * FX_STAGE);
        const uint32_t aHi = st + (uint32_t)((wm + arow) * 128);
        const uint32_t aLo = aHi + FX_SA;
        const uint32_t bHi = st + 2 * FX_SA + (uint32_t)((wn + brow) * 128);
        const uint32_t bLo = bHi + FX_SB;

#pragma unroll
        for (int kk = 0; kk < 4; ++kk) {
            const uint32_t ka = (uint32_t)(kk * 32 + akb) ^ swx;
            const uint32_t kb2 = (uint32_t)(kk * 32 + bkb) ^ swx;
            uint32_t ah[2][4], al[2][4], bh[2][4], bl[2][4];
#pragma unroll
            for (int mi = 0; mi < 2; ++mi) {
                ldsm4(ah[mi], aHi + mi * 2048 + ka);
                ldsm4(al[mi], aLo + mi * 2048 + ka);
            }
#pragma unroll
            for (int nj = 0; nj < 2; ++nj) {
                ldsm4(bh[nj], bHi + nj * 2048 + kb2);
                ldsm4(bl[nj], bLo + nj * 2048 + kb2);
            }
#pragma unroll
            for (int mi = 0; mi < 2; ++mi)
#pragma unroll
                for (int ni = 0; ni < 4; ++ni)
                    mma16816(acc[mi][ni], ah[mi],
                             bh[ni >> 1][2 * (ni & 1)], bh[ni >> 1][2 * (ni & 1) + 1]);
#pragma unroll
            for (int mi = 0; mi < 2; ++mi)
#pragma unroll
                for (int ni = 0; ni < 4; ++ni)
                    mma16816(acc[mi][ni], ah[mi],
                             bl[ni >> 1][2 * (ni & 1)], bl[ni >> 1][2 * (ni & 1) + 1]);
#pragma unroll
            for (int mi = 0; mi < 2; ++mi)
#pragma unroll
                for (int ni = 0; ni < 4; ++ni)
                    mma16816(acc[mi][ni], al[mi],
                             bh[ni >> 1][2 * (ni & 1)], bh[ni >> 1][2 * (ni & 1) + 1]);
        }
        __syncthreads();             // S2: stage s free for reuse
    }

    const int g = lane >> 2, tg = lane & 3;
#pragma unroll
    for (int mi = 0; mi < 2; ++mi) {
#pragma unroll
        for (int ni = 0; ni < 4; ++ni) {
            const size_t r0 = bm + (size_t)(wm + mi * 16 + g);
            const size_t r1 = r0 + 8;
            const int c0 = bn + wn + ni * 8 + 2 * tg;
            float b0 = bih[c0] + bhh[c0];
            float b1 = bih[c0 + 1] + bhh[c0 + 1];
            *(float2*)(out_f + r0 * HH + c0) =
                make_float2(acc[mi][ni][0] + b0, acc[mi][ni][1] + b1);
            *(float2*)(out_f + r1 * HH + c0) =
                make_float2(acc[mi][ni][2] + b0, acc[mi][ni][3] + b1);
        }
    }
}

// -------------------- persistent recurrence kernel (round-11, proven) ------
#define NCTA 128
#define SMB 0                 // W_hh: hi [0,64K), lo [64K,128K); chunk stride 8K
#define SMB_SPLIT 65536
#define SMB_CHUNK 8192
#define SMA 131072            // A: + half*32768 + chunk*4096 (hi +0, lo +2048)
#define SMA_HALF 32768
#define SMA_CHUNK 4096
#define SMXP 196608           // xp: + half*4096 (16x64 f32)
#define SMMISC 204800         // [0,8): fb per half; [16,80): sready[2][8]
#define PSMEM 204928

__global__ void __launch_bounds__(256, 1)
rnn_persistent_kernel(const float* __restrict__ xp,
                      const __nv_bfloat16* __restrict__ whh_h,
                      const __nv_bfloat16* __restrict__ whh_l,
                      __nv_bfloat16* __restrict__ hhi_base,
                      __nv_bfloat16* __restrict__ hlo_base,
                      float* __restrict__ out)
{
    extern __shared__ char smem[];
    const uint32_t sb = smem_u32(smem);
    const int tid = threadIdx.x;
    const int half = tid >> 7;
    const int htid = tid & 127;
    const int lane = tid & 31;
    const int gidx = blockIdx.x >> 3;       // 0..15
    const int ntile = blockIdx.x & 7;       // 0..7
    const int rg = gidx + half * 16;        // rowgroup 0..31
    const size_t bm = (size_t)rg * 16;      // global row base (16 rows)
    const int bn = ntile * 64;
    const int wn = (htid >> 5) * 16;        // 4 warps/half, WN=16
    const int barid = 1 + half;

    const uint32_t aOff  = (uint32_t)(SMA + half * SMA_HALF);
    const uint32_t aAddr = sb + aOff;
    const uint32_t selfOff = aOff + (uint32_t)(ntile * SMA_CHUNK);
    const uint32_t xpAddr  = sb + (uint32_t)(SMXP + half * 4096);
    const uint32_t srBase  = sb + (uint32_t)(SMMISC + 16 + half * 32);

    if (htid == 0) {
        unsigned fb0;
        asm volatile("ld.volatile.global.u32 %0, [%1];"
                     : "=r"(fb0) : "l"(&g_flag[rg][ntile * 32]));
        *(unsigned*)(smem + SMMISC + half * 4) = fb0;
    }
    if (tid < 16) *(unsigned*)(smem + SMMISC + 16 + tid * 4) = 0;

    // resident W_hh tiles (rows bn..bn+64, all K), both splits (full CTA)
#pragma unroll
    for (int i = 0; i < 32; ++i) {
        int v = i * 256 + tid;
        int split = v >> 12;
        int rem = v & 4095;
        int chunk = rem >> 9;
        int rr = rem & 511;
        int row = rr >> 3, gq = rr & 7;
        const __nv_bfloat16* src = (split ? whh_l : whh_h);
        uint32_t dst = sb + SMB + split * SMB_SPLIT + chunk * SMB_CHUNK
                     + row * 128 + (uint32_t)((gq * 16) ^ ((row & 7) * 16));
        cp16(dst, src + (size_t)(bn + row) * HH + chunk * 64 + gq * 8);
    }
    CP_COMMIT();

    auto sts4 = [&](uint32_t base, int row, int lc, uint32_t val) {
        uint32_t bc = (uint32_t)(lc * 2);
        uint32_t off = (uint32_t)(row * 128)
                     + ((bc & ~15u) ^ (((uint32_t)(row & 7)) << 4)) + (bc & 15u);
        *(uint32_t*)(smem + base + off) = val;
    };

    // step 0: h1 = tanh(xp_0) -> buf 0 + self smem chunk
#pragma unroll
    for (int i = 0; i < 2; ++i) {
        int v = i * 128 + htid;
        int row = v >> 4, c4 = v & 15;
        const float4 x = *(const float4*)(xp + (bm + row) * HH + bn + c4 * 4);
        float v0 = fast_tanh(x.x), v1 = fast_tanh(x.y);
        float v2 = fast_tanh(x.z), v3 = fast_tanh(x.w);
        __nv_bfloat16 h0, l0, h1, l1, h2, l2, h3, l3;
        split1(v0, h0, l0); split1(v1, h1, l1);
        split1(v2, h2, l2); split1(v3, h3, l3);
        __nv_bfloat162 hp0(h0, h1), hp1(h2, h3), lp0(l0, l1), lp1(l2, l3);
        size_t off = (bm + row) * HH + bn + c4 * 4;
        *(uint2*)(hhi_base + off) = make_uint2(*(uint32_t*)&hp0, *(uint32_t*)&hp1);
        *(uint2*)(hlo_base + off) = make_uint2(*(uint32_t*)&lp0, *(uint32_t*)&lp1);
        sts4(selfOff, row, c4 * 4, *(uint32_t*)&hp0);
        sts4(selfOff, row, c4 * 4 + 2, *(uint32_t*)&hp1);
        sts4(selfOff + 2048, row, c4 * 4, *(uint32_t*)&lp0);
        sts4(selfOff + 2048, row, c4 * 4 + 2, *(uint32_t*)&lp1);
    }
    CP_WAIT(0);
    __syncthreads();
    const unsigned fb = *(const unsigned*)(smem + SMMISC + half * 4);
    if (htid == 0)
        asm volatile("red.release.gpu.global.add.u32 [%0], %1;"
                     :: "l"(&g_flag[rg][ntile * 32]), "r"(1u) : "memory");

    const int sub = lane >> 3, li = lane & 7;
    const int arow = (sub & 1) * 8 + li;
    const int akb  = (sub >> 1) * 16;
    const int brow = (sub >> 1) * 8 + li;
    const int bkb  = (sub & 1) * 16;
    const uint32_t swx = (uint32_t)(li * 16);
    const int gl = lane >> 2, tg = lane & 3;

    for (int t = 1; t < TT; ++t) {
        const __nv_bfloat16* Ah = hhi_base + (size_t)((t - 1) & 1) * BH;
        const __nv_bfloat16* Al = hlo_base + (size_t)((t - 1) & 1) * BH;
        __nv_bfloat16* Oh = hhi_base + (size_t)(t & 1) * BH;
        __nv_bfloat16* Ol = hlo_base + (size_t)(t & 1) * BH;
        const float* xpt = xp + (size_t)t * BH;

        float acc[2][4];
#pragma unroll
        for (int ni = 0; ni < 2; ++ni)
#pragma unroll
            for (int q = 0; q < 4; ++q) acc[ni][q] = 0.0f;

        auto compute_chunk = [&](int c) {
            const uint32_t aHi = aAddr + c * SMA_CHUNK + (uint32_t)(arow * 128);
            const uint32_t aLo = aHi + 2048;
            const uint32_t bHi = sb + SMB + c * SMB_CHUNK + (uint32_t)((wn + brow) * 128);
            const uint32_t bLo = bHi + SMB_SPLIT;
#pragma unroll
            for (int kk = 0; kk < 4; ++kk) {
                const uint32_t ka  = (uint32_t)(kk * 32 + akb) ^ swx;
                const uint32_t kb2 = (uint32_t)(kk * 32 + bkb) ^ swx;
                uint32_t ah[4], al4[4], bh[4], bl[4];
                ldsm4(ah, aHi + ka);
                ldsm4(al4, aLo + ka);
                ldsm4(bh, bHi + kb2);
                ldsm4(bl, bLo + kb2);
#pragma unroll
                for (int ni = 0; ni < 2; ++ni)
                    mma16816(acc[ni], ah, bh[2 * ni], bh[2 * ni + 1]);
#pragma unroll
                for (int ni = 0; ni < 2; ++ni)
                    mma16816(acc[ni], ah, bl[2 * ni], bl[2 * ni + 1]);
#pragma unroll
                for (int ni = 0; ni < 2; ++ni)
                    mma16816(acc[ni], al4, bh[2 * ni], bh[2 * ni + 1]);
            }
        };

        // phase -1: issue xp tile load (group 1)
        {
#pragma unroll
            for (int i = 0; i < 2; ++i) {
                int v = i * 128 + htid;
                int row = v >> 4, gq = v & 15;
                cp16(xpAddr + row * 256 + gq * 16,
                     xpt + (bm + row) * HH + bn + gq * 4);
            }
            CP_COMMIT();
        }

        // phase 0: self chunk
        compute_chunk(ntile);

        // phase 1: eager poll + publish (threads 0..6)
        if (htid < 7) {
            const int c = (ntile + 1 + htid) & 7;
            const unsigned* fl = &g_flag[rg][c * 32];
            const unsigned target = fb + (unsigned)t;
            unsigned v;
            do {
                asm volatile("ld.acquire.gpu.global.u32 %0, [%1];" : "=r"(v) : "l"(fl));
            } while ((int)(v - target) < 0);
            st_rel_shared(srBase + (uint32_t)((htid + 1) * 4), (unsigned)t);
        }

        // phase 2: eager per-chunk issue
#pragma unroll
        for (int j = 1; j < 8; ++j) {
            const uint32_t sr = srBase + (uint32_t)(j * 4);
            while ((int)(ld_acq_shared(sr) - (unsigned)t) < 0) { }
            const int c = (ntile + j) & 7;
            const uint32_t base = aAddr + c * SMA_CHUNK;
#pragma unroll
            for (int i = 0; i < 2; ++i) {
                int v = i * 128 + htid;
                int split = v >> 7;
                int rr = v & 127;
                int row = rr >> 3, gq = rr & 7;
                const __nv_bfloat16* src = (split ? Al : Ah);
                uint32_t dst = base + split * 2048 + row * 128
                             + (uint32_t)((gq * 16) ^ ((row & 7) * 16));
                cp16(dst, src + (bm + (size_t)row) * HH + c * 64 + gq * 8);
            }
            CP_COMMIT();
        }

        // phase 3: two-stage waits + peer chunk computes
        CP_WAIT(4);
        BARH(barid);
        compute_chunk((ntile + 1) & 7);
        compute_chunk((ntile + 2) & 7);
        compute_chunk((ntile + 3) & 7);
        CP_WAIT(0);
        BARH(barid);
        compute_chunk((ntile + 4) & 7);
        compute_chunk((ntile + 5) & 7);
        compute_chunk((ntile + 6) & 7);
        compute_chunk((ntile + 7) & 7);

        // phase 4: epilogue
        const float* sXP = (const float*)(smem + SMXP + half * 4096);
#pragma unroll
        for (int ni = 0; ni < 2; ++ni) {
            const int lr0 = gl;
            const int lc  = wn + ni * 8 + 2 * tg;
            const size_t r0 = bm + (size_t)lr0;
            const size_t r1 = r0 + 8;
            const int c0 = bn + lc;
            float2 x0 = *(const float2*)(sXP + lr0 * 64 + lc);
            float2 x1 = *(const float2*)(sXP + (lr0 + 8) * 64 + lc);
            float v0 = fast_tanh(acc[ni][0] + x0.x);
            float v1 = fast_tanh(acc[ni][1] + x0.y);
            float v2 = fast_tanh(acc[ni][2] + x1.x);
            float v3 = fast_tanh(acc[ni][3] + x1.y);
            if (t == TT - 1) {
                *(float2*)(out + r0 * HH + c0) = make_float2(v0, v1);
                *(float2*)(out + r1 * HH + c0) = make_float2(v2, v3);
            } else {
                __nv_bfloat16 h0, l0, h1, l1, h2, l2, h3, l3;
                split1(v0, h0, l0); split1(v1, h1, l1);
                split1(v2, h2, l2); split1(v3, h3, l3);
                __nv_bfloat162 hp0(h0, h1), hp1(h2, h3), lp0(l0, l1), lp1(l2, l3);
                *(uint32_t*)(Oh + r0 * HH + c0) = *(uint32_t*)&hp0;
                *(uint32_t*)(Ol + r0 * HH + c0) = *(uint32_t*)&lp0;
                *(uint32_t*)(Oh + r1 * HH + c0) = *(uint32_t*)&hp1;
                *(uint32_t*)(Ol + r1 * HH + c0) = *(uint32_t*)&lp1;
                sts4(selfOff, lr0, lc, *(uint32_t*)&hp0);
                sts4(selfOff + 2048, lr0, lc, *(uint32_t*)&lp0);
                sts4(selfOff, lr0 + 8, lc, *(uint32_t*)&hp1);
                sts4(selfOff + 2048, lr0 + 8, lc, *(uint32_t*)&lp1);
            }
        }

        BARH(barid);
        if (htid == 0 && t < TT - 1)
            asm volatile("red.release.gpu.global.add.u32 [%0], %1;"
                         :: "l"(&g_flag[rg][ntile * 32]), "r"(1u) : "memory");
    }
}

// -------------------- launcher ---------------------------------------------
extern "C" void kernel_launch(void* const* d_in, const int* in_sizes, int n_in,
                              void* d_out, int out_size)
{
    const float* X   = (const float*)d_in[0];
    const float* Wih = (const float*)d_in[1];
    const float* Whh = (const float*)d_in[2];
    const float* bih = (const float*)d_in[3];
    const float* bhh = (const float*)d_in[4];
    float* out = (float*)d_out;

    float* xp;
    __nv_bfloat16 *wih_h, *wih_l, *whh_h, *whh_l, *hhi, *hlo;
    cudaGetSymbolAddress((void**)&xp, g_xp);
    cudaGetSymbolAddress((void**)&wih_h, g_wih_h);
    cudaGetSymbolAddress((void**)&wih_l, g_wih_l);
    cudaGetSymbolAddress((void**)&whh_h, g_whh_h);
    cudaGetSymbolAddress((void**)&whh_l, g_whh_l);
    cudaGetSymbolAddress((void**)&hhi, g_hhi);
    cudaGetSymbolAddress((void**)&hlo, g_hlo);

    cudaFuncSetAttribute(xp_gemm_fx,
                         cudaFuncAttributeMaxDynamicSharedMemorySize, FX_SMEM);
    cudaFuncSetAttribute(rnn_persistent_kernel,
                         cudaFuncAttributeMaxDynamicSharedMemorySize, PSMEM);

    // 1) hi/lo splits of weights only (X split fused into xp GEMM)
    split_kernel<<<128, 256>>>(Wih, wih_h, wih_l, HH * DD / 4);
    split_kernel<<<128, 256>>>(Whh, whh_h, whh_l, HH * HH / 4);

    // 2) xp = X @ Wih^T + (b_ih + b_hh), fused fp32->hi/lo conversion
    {
        dim3 g(HH / 128, (TT * BB) / 64);  // (4, 4096)
        xp_gemm_fx<<<g, 256, FX_SMEM>>>(X, wih_h, wih_l, bih, bhh, xp);
    }

    // 3) entire recurrence in one persistent kernel (round-11 proven)
    rnn_persistent_kernel<<<NCTA, 256, PSMEM>>>(xp, whh_h, whh_l, hhi, hlo, out);
}

// round 14
// speedup vs baseline: 1.5071x; 1.5071x over previous
#include <cuda_runtime.h>
#include <cuda_bf16.h>
#include <math.h>
#include <stdint.h>

// Problem dims (fixed)
#define TT 512
#define BB 512
#define DD 512
#define HH 512
#define BH (BB * HH)  // 262144

// -------------------- device scratch (no allocations allowed) --------------
__device__ float          g_xp[(size_t)TT * BH];            // 512 MB
__device__ __nv_bfloat16  g_wih_h[HH * DD], g_wih_l[HH * DD];
__device__ __nv_bfloat16  g_whh_h[HH * HH], g_whh_l[HH * HH];
__device__ __nv_bfloat16  g_hhi[2][BH], g_hlo[2][BH];

// producer flags: flag[rg][n*32], rg = 0..31 (16-row groups), n = 0..7.
// Monotonic; every owner increments exactly 511 times per launch.
__device__ unsigned g_flag[32][8 * 32];

// -------------------- PTX helpers (sm_80-level only; no 'a' features) ------
__device__ __forceinline__ uint32_t smem_u32(const void* p) {
    uint32_t a;
    asm("{ .reg .u64 t; cvta.to.shared.u64 t, %1; cvt.u32.u64 %0, t; }" : "=r"(a) : "l"(p));
    return a;
}
__device__ __forceinline__ void cp16(uint32_t s, const void* g) {
    asm volatile("cp.async.cg.shared.global [%0], [%1], 16;" :: "r"(s), "l"(g));
}
#define CP_COMMIT() asm volatile("cp.async.commit_group;" ::: "memory")
#define CP_WAIT(n)  asm volatile("cp.async.wait_group %0;" :: "n"(n) : "memory")
#define BARH(id)    asm volatile("bar.sync %0, 128;" :: "r"(id) : "memory")

__device__ __forceinline__ void st_rel_shared(uint32_t addr, unsigned v) {
    asm volatile("st.release.cta.shared.u32 [%0], %1;" :: "r"(addr), "r"(v) : "memory");
}
__device__ __forceinline__ unsigned ld_acq_shared(uint32_t addr) {
    unsigned v;
    asm volatile("ld.acquire.cta.shared.u32 %0, [%1];" : "=r"(v) : "r"(addr) : "memory");
    return v;
}

__device__ __forceinline__ void ldsm4(uint32_t* r, uint32_t addr) {
    asm volatile("ldmatrix.sync.aligned.m8n8.x4.shared.b16 {%0,%1,%2,%3}, [%4];"
                 : "=r"(r[0]), "=r"(r[1]), "=r"(r[2]), "=r"(r[3]) : "r"(addr));
}
__device__ __forceinline__ void mma16816(float* d, const uint32_t* a, uint32_t b0, uint32_t b1) {
    asm volatile("mma.sync.aligned.m16n8k16.row.col.f32.bf16.bf16.f32 "
                 "{%0,%1,%2,%3}, {%4,%5,%6,%7}, {%8,%9}, {%0,%1,%2,%3};"
                 : "+f"(d[0]), "+f"(d[1]), "+f"(d[2]), "+f"(d[3])
                 : "r"(a[0]), "r"(a[1]), "r"(a[2]), "r"(a[3]), "r"(b0), "r"(b1));
}

// fast tanh: 1 - 2/(e^{2x}+1) via MUFU (abs err ~1e-6; saturates correctly)
__device__ __forceinline__ float fast_tanh(float x) {
    float e = __expf(2.0f * x);
    return 1.0f - __fdividef(2.0f, e + 1.0f);
}

// -------------------- split helpers ----------------------------------------
__device__ __forceinline__ void split1(float x, __nv_bfloat16& h, __nv_bfloat16& l) {
    h = __float2bfloat16_rn(x);
    l = __float2bfloat16_rn(x - __bfloat162float(h));
}

__global__ __launch_bounds__(256) void split_kernel(const float* __restrict__ src,
                                                    __nv_bfloat16* __restrict__ hi,
                                                    __nv_bfloat16* __restrict__ lo, int n4) {
    for (int i = blockIdx.x * blockDim.x + threadIdx.x; i < n4; i += gridDim.x * blockDim.x) {
        float4 v = ((const float4*)src)[i];
        __nv_bfloat16 h0, h1, h2, h3, l0, l1, l2, l3;
        split1(v.x, h0, l0); split1(v.y, h1, l1);
        split1(v.z, h2, l2); split1(v.w, h3, l3);
        __nv_bfloat162* ph = (__nv_bfloat162*)hi;
        __nv_bfloat162* pl = (__nv_bfloat162*)lo;
        ph[i * 2] = __nv_bfloat162(h0, h1); ph[i * 2 + 1] = __nv_bfloat162(h2, h3);
        pl[i * 2] = __nv_bfloat162(l0, l1); pl[i * 2 + 1] = __nv_bfloat162(l2, l3);
    }
}

// -------------------- async tile loader (64-col bf16 tiles) ----------------
template <int ROWS, int THREADS>
__device__ __forceinline__ void load_tile_async(const __nv_bfloat16* __restrict__ g,
                                                size_t row0, int kbase,
                                                uint32_t sdst, int tid) {
    constexpr int TOT = ROWS * 8;  // 16B granules
#pragma unroll
    for (int i = 0; i < TOT / THREADS; ++i) {
        int v = i * THREADS + tid;
        int row = v >> 3, g16 = v & 7;
        uint32_t off = (uint32_t)(row * 128 + ((g16 * 16) ^ ((row & 7) * 16)));
        cp16(sdst + off, g + (row0 + (size_t)row) * HH + kbase + g16 * 8);
    }
}

// -------------------- xp GEMM with fused X conversion (v2: no reg pressure) -
// xp[M, N] = X[M,K](fp32) @ (Wih hi/lo)[N,K]^T + bih + bhh; K=512, BK=64.
// BM=64, BN=128, 256 threads, 2 CTAs/SM. Per chunk: X fp32 -> SW128 staging
// via cp.async; short staging->regs->(bar)->in-place hi/lo STS conversion;
// then the proven round-8 compute body. Stage = 16K (staging/A) + 32K (B).
#define FX_SA 8192
#define FX_STAGE 49152
#define FX_SMEM (2 * FX_STAGE)   // 98304

__global__ void __launch_bounds__(256, 2)
xp_gemm_fx(const float* __restrict__ X,
           const __nv_bfloat16* __restrict__ Bhi, const __nv_bfloat16* __restrict__ Blo,
           const float* __restrict__ bih, const float* __restrict__ bhh,
           float* __restrict__ out_f)
{
    extern __shared__ char smem[];
    const uint32_t sbase = smem_u32(smem);
    const int tid = threadIdx.x;
    const int wid = tid >> 5, lane = tid & 31;
    const size_t bm = (size_t)blockIdx.y * 64;
    const int bn = blockIdx.x * 128;
    const int wm = (wid & 1) * 32;          // BM/WM = 2
    const int wn = (wid >> 1) * 32;         // BN/WN = 4

    float acc[2][4][4];
#pragma unroll
    for (int mi = 0; mi < 2; ++mi)
#pragma unroll
        for (int ni = 0; ni < 4; ++ni)
#pragma unroll
            for (int q = 0; q < 4; ++q) acc[mi][ni][q] = 0.0f;

    const int sub = lane >> 3, li = lane & 7;
    const int arow = (sub & 1) * 8 + li;
    const int akb  = (sub >> 1) * 16;
    const int brow = (sub >> 1) * 8 + li;
    const int bkb  = (sub & 1) * 16;
    const uint32_t swx = (uint32_t)(li * 16);

    // conversion thread mapping: staging row srow = tid>>1 (128 rows x 128B),
    // each thread covers 16 fp32 = half a staging row.
    const int csrow = tid >> 1, chf = tid & 1;
    const int clr = csrow >> 1, cch = csrow & 1;   // logical row, col-half

    auto issue_grp = [&](int c, int s) {
        const uint32_t st = sbase + (uint32_t)(s * FX_STAGE);
        const int kb = c * 64;
        // X fp32: chunk 64x64 fp32 as 128 staging rows x 128B, SW128 swizzle
#pragma unroll
        for (int i = 0; i < 4; ++i) {
            int gi = i * 256 + tid;          // 1024 granules
            int srow = gi >> 3, gq = gi & 7;
            int lr = srow >> 1, ch = srow & 1;
            uint32_t off = (uint32_t)(srow * 128 + ((gq * 16) ^ ((srow & 7) * 16)));
            cp16(st + off, X + (bm + (size_t)lr) * DD + kb + ch * 32 + gq * 4);
        }
        load_tile_async<128, 256>(Bhi, (size_t)bn, kb, st + 16384, tid);
        load_tile_async<128, 256>(Blo, (size_t)bn, kb, st + 32768, tid);
        CP_COMMIT();
    };

    issue_grp(0, 0);

    for (int c = 0; c < 8; ++c) {
        const int s = c & 1;
        if (c + 1 < 8) {
            issue_grp(c + 1, s ^ 1);   // stage s^1 reusable: freed by sync4(c-1)
            CP_WAIT(1);
        } else {
            CP_WAIT(0);
        }
        __syncthreads();               // sync1: staging(s) + B(s) visible

        // readback 16 fp32 (own half staging row) — conflict-free
        float4 xv[4];
        {
            const char* stg = smem + s * FX_STAGE;
            const uint32_t rb = (uint32_t)(csrow * 128);
            const uint32_t s16 = (uint32_t)((csrow & 7) * 16);
#pragma unroll
            for (int k = 0; k < 4; ++k) {
                uint32_t gq = (uint32_t)(chf * 4 + k);
                xv[k] = *(const float4*)(stg + rb + ((gq * 16) ^ s16));
            }
        }
        __syncthreads();               // sync2: all staging reads done

        // convert + in-place store: hi at [0,8K), lo at [8K,16K)
        {
            uint32_t hi[8], lo[8];
#pragma unroll
            for (int k = 0; k < 4; ++k) {
                __nv_bfloat16 h0, l0, h1, l1, h2, l2, h3, l3;
                split1(xv[k].x, h0, l0); split1(xv[k].y, h1, l1);
                split1(xv[k].z, h2, l2); split1(xv[k].w, h3, l3);
                __nv_bfloat162 hp0(h0, h1), hp1(h2, h3), lp0(l0, l1), lp1(l2, l3);
                hi[k * 2] = *(uint32_t*)&hp0; hi[k * 2 + 1] = *(uint32_t*)&hp1;
                lo[k * 2] = *(uint32_t*)&lp0; lo[k * 2 + 1] = *(uint32_t*)&lp1;
            }
            const uint32_t ga = (uint32_t)(cch * 4 + chf * 2);  // even granule
            const uint32_t s16 = (uint32_t)((clr & 7) * 16);
            const uint32_t off = (uint32_t)(clr * 128) + ((ga * 16) ^ s16);
            const uint32_t off2 = off ^ 16;                      // granule ga+1
            char* stg = smem + s * FX_STAGE;
            *(uint4*)(stg + off)  = make_uint4(hi[0], hi[1], hi[2], hi[3]);
            *(uint4*)(stg + off2) = make_uint4(hi[4], hi[5], hi[6], hi[7]);
            *(uint4*)(stg + FX_SA + off)  = make_uint4(lo[0], lo[1], lo[2], lo[3]);
            *(uint4*)(stg + FX_SA + off2) = make_uint4(lo[4], lo[5], lo[6], lo[7]);
        }
        __syncthreads();               // sync3: A(s) hi/lo ready

        const uint32_t st = sbase + (uint32_t)(s * FX_STAGE);
        const uint32_t aHi = st + (uint32_t)((wm + arow) * 128);
        const uint32_t aLo = aHi + FX_SA;
        const uint32_t bHi = st + 16384 + (uint32_t)((wn + brow) * 128);
        const uint32_t bLo = bHi + 16384;

#pragma unroll
        for (int kk = 0; kk < 4; ++kk) {
            const uint32_t ka = (uint32_t)(kk * 32 + akb) ^ swx;
            const uint32_t kb2 = (uint32_t)(kk * 32 + bkb) ^ swx;
            uint32_t ah[2][4], al[2][4], bh[2][4], bl[2][4];
#pragma unroll
            for (int mi = 0; mi < 2; ++mi) {
                ldsm4(ah[mi], aHi + mi * 2048 + ka);
                ldsm4(al[mi], aLo + mi * 2048 + ka);
            }
#pragma unroll
            for (int nj = 0; nj < 2; ++nj) {
                ldsm4(bh[nj], bHi + nj * 2048 + kb2);
                ldsm4(bl[nj], bLo + nj * 2048 + kb2);
            }
#pragma unroll
            for (int mi = 0; mi < 2; ++mi)
#pragma unroll
                for (int ni = 0; ni < 4; ++ni)
                    mma16816(acc[mi][ni], ah[mi],
                             bh[ni >> 1][2 * (ni & 1)], bh[ni >> 1][2 * (ni & 1) + 1]);
#pragma unroll
            for (int mi = 0; mi < 2; ++mi)
#pragma unroll
                for (int ni = 0; ni < 4; ++ni)
                    mma16816(acc[mi][ni], ah[mi],
                             bl[ni >> 1][2 * (ni & 1)], bl[ni >> 1][2 * (ni & 1) + 1]);
#pragma unroll
            for (int mi = 0; mi < 2; ++mi)
#pragma unroll
                for (int ni = 0; ni < 4; ++ni)
                    mma16816(acc[mi][ni], al[mi],
                             bh[ni >> 1][2 * (ni & 1)], bh[ni >> 1][2 * (ni & 1) + 1]);
        }
        __syncthreads();               // sync4: stage s free for reuse
    }

    const int g = lane >> 2, tg = lane & 3;
#pragma unroll
    for (int mi = 0; mi < 2; ++mi) {
#pragma unroll
        for (int ni = 0; ni < 4; ++ni) {
            const size_t r0 = bm + (size_t)(wm + mi * 16 + g);
            const size_t r1 = r0 + 8;
            const int c0 = bn + wn + ni * 8 + 2 * tg;
            float b0 = bih[c0] + bhh[c0];
            float b1 = bih[c0 + 1] + bhh[c0 + 1];
            *(float2*)(out_f + r0 * HH + c0) =
                make_float2(acc[mi][ni][0] + b0, acc[mi][ni][1] + b1);
            *(float2*)(out_f + r1 * HH + c0) =
                make_float2(acc[mi][ni][2] + b0, acc[mi][ni][3] + b1);
        }
    }
}

// -------------------- persistent recurrence kernel (round-11, proven) ------
#define NCTA 128
#define SMB 0                 // W_hh: hi [0,64K), lo [64K,128K); chunk stride 8K
#define SMB_SPLIT 65536
#define SMB_CHUNK 8192
#define SMA 131072            // A: + half*32768 + chunk*4096 (hi +0, lo +2048)
#define SMA_HALF 32768
#define SMA_CHUNK 4096
#define SMXP 196608           // xp: + half*4096 (16x64 f32)
#define SMMISC 204800         // [0,8): fb per half; [16,80): sready[2][8]
#define PSMEM 204928

__global__ void __launch_bounds__(256, 1)
rnn_persistent_kernel(const float* __restrict__ xp,
                      const __nv_bfloat16* __restrict__ whh_h,
                      const __nv_bfloat16* __restrict__ whh_l,
                      __nv_bfloat16* __restrict__ hhi_base,
                      __nv_bfloat16* __restrict__ hlo_base,
                      float* __restrict__ out)
{
    extern __shared__ char smem[];
    const uint32_t sb = smem_u32(smem);
    const int tid = threadIdx.x;
    const int half = tid >> 7;
    const int htid = tid & 127;
    const int lane = tid & 31;
    const int gidx = blockIdx.x >> 3;       // 0..15
    const int ntile = blockIdx.x & 7;       // 0..7
    const int rg = gidx + half * 16;        // rowgroup 0..31
    const size_t bm = (size_t)rg * 16;      // global row base (16 rows)
    const int bn = ntile * 64;
    const int wn = (htid >> 5) * 16;        // 4 warps/half, WN=16
    const int barid = 1 + half;

    const uint32_t aOff  = (uint32_t)(SMA + half * SMA_HALF);
    const uint32_t aAddr = sb + aOff;
    const uint32_t selfOff = aOff + (uint32_t)(ntile * SMA_CHUNK);
    const uint32_t xpAddr  = sb + (uint32_t)(SMXP + half * 4096);
    const uint32_t srBase  = sb + (uint32_t)(SMMISC + 16 + half * 32);

    if (htid == 0) {
        unsigned fb0;
        asm volatile("ld.volatile.global.u32 %0, [%1];"
                     : "=r"(fb0) : "l"(&g_flag[rg][ntile * 32]));
        *(unsigned*)(smem + SMMISC + half * 4) = fb0;
    }
    if (tid < 16) *(unsigned*)(smem + SMMISC + 16 + tid * 4) = 0;

    // resident W_hh tiles (rows bn..bn+64, all K), both splits (full CTA)
#pragma unroll
    for (int i = 0; i < 32; ++i) {
        int v = i * 256 + tid;
        int split = v >> 12;
        int rem = v & 4095;
        int chunk = rem >> 9;
        int rr = rem & 511;
        int row = rr >> 3, gq = rr & 7;
        const __nv_bfloat16* src = (split ? whh_l : whh_h);
        uint32_t dst = sb + SMB + split * SMB_SPLIT + chunk * SMB_CHUNK
                     + row * 128 + (uint32_t)((gq * 16) ^ ((row & 7) * 16));
        cp16(dst, src + (size_t)(bn + row) * HH + chunk * 64 + gq * 8);
    }
    CP_COMMIT();

    auto sts4 = [&](uint32_t base, int row, int lc, uint32_t val) {
        uint32_t bc = (uint32_t)(lc * 2);
        uint32_t off = (uint32_t)(row * 128)
                     + ((bc & ~15u) ^ (((uint32_t)(row & 7)) << 4)) + (bc & 15u);
        *(uint32_t*)(smem + base + off) = val;
    };

    // step 0: h1 = tanh(xp_0) -> buf 0 + self smem chunk
#pragma unroll
    for (int i = 0; i < 2; ++i) {
        int v = i * 128 + htid;
        int row = v >> 4, c4 = v & 15;
        const float4 x = *(const float4*)(xp + (bm + row) * HH + bn + c4 * 4);
        float v0 = fast_tanh(x.x), v1 = fast_tanh(x.y);
        float v2 = fast_tanh(x.z), v3 = fast_tanh(x.w);
        __nv_bfloat16 h0, l0, h1, l1, h2, l2, h3, l3;
        split1(v0, h0, l0); split1(v1, h1, l1);
        split1(v2, h2, l2); split1(v3, h3, l3);
        __nv_bfloat162 hp0(h0, h1), hp1(h2, h3), lp0(l0, l1), lp1(l2, l3);
        size_t off = (bm + row) * HH + bn + c4 * 4;
        *(uint2*)(hhi_base + off) = make_uint2(*(uint32_t*)&hp0, *(uint32_t*)&hp1);
        *(uint2*)(hlo_base + off) = make_uint2(*(uint32_t*)&lp0, *(uint32_t*)&lp1);
        sts4(selfOff, row, c4 * 4, *(uint32_t*)&hp0);
        sts4(selfOff, row, c4 * 4 + 2, *(uint32_t*)&hp1);
        sts4(selfOff + 2048, row, c4 * 4, *(uint32_t*)&lp0);
        sts4(selfOff + 2048, row, c4 * 4 + 2, *(uint32_t*)&lp1);
    }
    CP_WAIT(0);
    __syncthreads();
    const unsigned fb = *(const unsigned*)(smem + SMMISC + half * 4);
    if (htid == 0)
        asm volatile("red.release.gpu.global.add.u32 [%0], %1;"
                     :: "l"(&g_flag[rg][ntile * 32]), "r"(1u) : "memory");

    const int sub = lane >> 3, li = lane & 7;
    const int arow = (sub & 1) * 8 + li;
    const int akb  = (sub >> 1) * 16;
    const int brow = (sub >> 1) * 8 + li;
    const int bkb  = (sub & 1) * 16;
    const uint32_t swx = (uint32_t)(li * 16);
    const int gl = lane >> 2, tg = lane & 3;

    for (int t = 1; t < TT; ++t) {
        const __nv_bfloat16* Ah = hhi_base + (size_t)((t - 1) & 1) * BH;
        const __nv_bfloat16* Al = hlo_base + (size_t)((t - 1) & 1) * BH;
        __nv_bfloat16* Oh = hhi_base + (size_t)(t & 1) * BH;
        __nv_bfloat16* Ol = hlo_base + (size_t)(t & 1) * BH;
        const float* xpt = xp + (size_t)t * BH;

        float acc[2][4];
#pragma unroll
        for (int ni = 0; ni < 2; ++ni)
#pragma unroll
            for (int q = 0; q < 4; ++q) acc[ni][q] = 0.0f;

        auto compute_chunk = [&](int c) {
            const uint32_t aHi = aAddr + c * SMA_CHUNK + (uint32_t)(arow * 128);
            const uint32_t aLo = aHi + 2048;
            const uint32_t bHi = sb + SMB + c * SMB_CHUNK + (uint32_t)((wn + brow) * 128);
            const uint32_t bLo = bHi + SMB_SPLIT;
#pragma unroll
            for (int kk = 0; kk < 4; ++kk) {
                const uint32_t ka  = (uint32_t)(kk * 32 + akb) ^ swx;
                const uint32_t kb2 = (uint32_t)(kk * 32 + bkb) ^ swx;
                uint32_t ah[4], al4[4], bh[4], bl[4];
                ldsm4(ah, aHi + ka);
                ldsm4(al4, aLo + ka);
                ldsm4(bh, bHi + kb2);
                ldsm4(bl, bLo + kb2);
#pragma unroll
                for (int ni = 0; ni < 2; ++ni)
                    mma16816(acc[ni], ah, bh[2 * ni], bh[2 * ni + 1]);
#pragma unroll
                for (int ni = 0; ni < 2; ++ni)
                    mma16816(acc[ni], ah, bl[2 * ni], bl[2 * ni + 1]);
#pragma unroll
                for (int ni = 0; ni < 2; ++ni)
                    mma16816(acc[ni], al4, bh[2 * ni], bh[2 * ni + 1]);
            }
        };

        // phase -1: issue xp tile load (group 1)
        {
#pragma unroll
            for (int i = 0; i < 2; ++i) {
                int v = i * 128 + htid;
                int row = v >> 4, gq = v & 15;
                cp16(xpAddr + row * 256 + gq * 16,
                     xpt + (bm + row) * HH + bn + gq * 4);
            }
            CP_COMMIT();
        }

        // phase 0: self chunk
        compute_chunk(ntile);

        // phase 1: eager poll + publish (threads 0..6)
        if (htid < 7) {
            const int c = (ntile + 1 + htid) & 7;
            const unsigned* fl = &g_flag[rg][c * 32];
            const unsigned target = fb + (unsigned)t;
            unsigned v;
            do {
                asm volatile("ld.acquire.gpu.global.u32 %0, [%1];" : "=r"(v) : "l"(fl));
            } while ((int)(v - target) < 0);
            st_rel_shared(srBase + (uint32_t)((htid + 1) * 4), (unsigned)t);
        }

        // phase 2: eager per-chunk issue
#pragma unroll
        for (int j = 1; j < 8; ++j) {
            const uint32_t sr = srBase + (uint32_t)(j * 4);
            while ((int)(ld_acq_shared(sr) - (unsigned)t) < 0) { }
            const int c = (ntile + j) & 7;
            const uint32_t base = aAddr + c * SMA_CHUNK;
#pragma unroll
            for (int i = 0; i < 2; ++i) {
                int v = i * 128 + htid;
                int split = v >> 7;
                int rr = v & 127;
                int row = rr >> 3, gq = rr & 7;
                const __nv_bfloat16* src = (split ? Al : Ah);
                uint32_t dst = base + split * 2048 + row * 128
                             + (uint32_t)((gq * 16) ^ ((row & 7) * 16));
                cp16(dst, src + (bm + (size_t)row) * HH + c * 64 + gq * 8);
            }
            CP_COMMIT();
        }

        // phase 3: two-stage waits + peer chunk computes
        CP_WAIT(4);
        BARH(barid);
        compute_chunk((ntile + 1) & 7);
        compute_chunk((ntile + 2) & 7);
        compute_chunk((ntile + 3) & 7);
        CP_WAIT(0);
        BARH(barid);
        compute_chunk((ntile + 4) & 7);
        compute_chunk((ntile + 5) & 7);
        compute_chunk((ntile + 6) & 7);
        compute_chunk((ntile + 7) & 7);

        // phase 4: epilogue
        const float* sXP = (const float*)(smem + SMXP + half * 4096);
#pragma unroll
        for (int ni = 0; ni < 2; ++ni) {
            const int lr0 = gl;
            const int lc  = wn + ni * 8 + 2 * tg;
            const size_t r0 = bm + (size_t)lr0;
            const size_t r1 = r0 + 8;
            const int c0 = bn + lc;
            float2 x0 = *(const float2*)(sXP + lr0 * 64 + lc);
            float2 x1 = *(const float2*)(sXP + (lr0 + 8) * 64 + lc);
            float v0 = fast_tanh(acc[ni][0] + x0.x);
            float v1 = fast_tanh(acc[ni][1] + x0.y);
            float v2 = fast_tanh(acc[ni][2] + x1.x);
            float v3 = fast_tanh(acc[ni][3] + x1.y);
            if (t == TT - 1) {
                *(float2*)(out + r0 * HH + c0) = make_float2(v0, v1);
                *(float2*)(out + r1 * HH + c0) = make_float2(v2, v3);
            } else {
                __nv_bfloat16 h0, l0, h1, l1, h2, l2, h3, l3;
                split1(v0, h0, l0); split1(v1, h1, l1);
                split1(v2, h2, l2); split1(v3, h3, l3);
                __nv_bfloat162 hp0(h0, h1), hp1(h2, h3), lp0(l0, l1), lp1(l2, l3);
                *(uint32_t*)(Oh + r0 * HH + c0) = *(uint32_t*)&hp0;
                *(uint32_t*)(Ol + r0 * HH + c0) = *(uint32_t*)&lp0;
                *(uint32_t*)(Oh + r1 * HH + c0) = *(uint32_t*)&hp1;
                *(uint32_t*)(Ol + r1 * HH + c0) = *(uint32_t*)&lp1;
                sts4(selfOff, lr0, lc, *(uint32_t*)&hp0);
                sts4(selfOff + 2048, lr0, lc, *(uint32_t*)&lp0);
                sts4(selfOff, lr0 + 8, lc, *(uint32_t*)&hp1);
                sts4(selfOff + 2048, lr0 + 8, lc, *(uint32_t*)&lp1);
            }
        }

        BARH(barid);
        if (htid == 0 && t < TT - 1)
            asm volatile("red.release.gpu.global.add.u32 [%0], %1;"
                         :: "l"(&g_flag[rg][ntile * 32]), "r"(1u) : "memory");
    }
}

// -------------------- launcher ---------------------------------------------
extern "C" void kernel_launch(void* const* d_in, const int* in_sizes, int n_in,
                              void* d_out, int out_size)
{
    const float* X   = (const float*)d_in[0];
    const float* Wih = (const float*)d_in[1];
    const float* Whh = (const float*)d_in[2];
    const float* bih = (const float*)d_in[3];
    const float* bhh = (const float*)d_in[4];
    float* out = (float*)d_out;

    float* xp;
    __nv_bfloat16 *wih_h, *wih_l, *whh_h, *whh_l, *hhi, *hlo;
    cudaGetSymbolAddress((void**)&xp, g_xp);
    cudaGetSymbolAddress((void**)&wih_h, g_wih_h);
    cudaGetSymbolAddress((void**)&wih_l, g_wih_l);
    cudaGetSymbolAddress((void**)&whh_h, g_whh_h);
    cudaGetSymbolAddress((void**)&whh_l, g_whh_l);
    cudaGetSymbolAddress((void**)&hhi, g_hhi);
    cudaGetSymbolAddress((void**)&hlo, g_hlo);

    cudaFuncSetAttribute(xp_gemm_fx,
                         cudaFuncAttributeMaxDynamicSharedMemorySize, FX_SMEM);
    cudaFuncSetAttribute(rnn_persistent_kernel,
                         cudaFuncAttributeMaxDynamicSharedMemorySize, PSMEM);

    // 1) hi/lo splits of weights only (X conversion fused into xp GEMM)
    split_kernel<<<128, 256>>>(Wih, wih_h, wih_l, HH * DD / 4);
    split_kernel<<<128, 256>>>(Whh, whh_h, whh_l, HH * HH / 4);

    // 2) xp = X @ Wih^T + (b_ih + b_hh), fused fp32 conversion
    {
        dim3 g(HH / 128, (TT * BB) / 64);  // (4, 4096)
        xp_gemm_fx<<<g, 256, FX_SMEM>>>(X, wih_h, wih_l, bih, bhh, xp);
    }

    // 3) entire recurrence in one persistent kernel (round-11 proven)
    rnn_persistent_kernel<<<NCTA, 256, PSMEM>>>(xp, whh_h, whh_l, hhi, hlo, out);
}

// round 15
// speedup vs baseline: 1.5193x; 1.0081x over previous
#include <cuda_runtime.h>
#include <cuda_bf16.h>
#include <math.h>
#include <stdint.h>

// Problem dims (fixed)
#define TT 512
#define BB 512
#define DD 512
#define HH 512
#define BH (BB * HH)  // 262144

// -------------------- device scratch (no allocations allowed) --------------
__device__ float          g_xp[(size_t)TT * BH];            // 512 MB
__device__ __nv_bfloat16  g_wih_h[HH * DD], g_wih_l[HH * DD];
__device__ __nv_bfloat16  g_whh_h[HH * HH], g_whh_l[HH * HH];
__device__ __nv_bfloat16  g_hhi[2][BH], g_hlo[2][BH];

// producer flags: flag[rg][n*32], rg = 0..31 (16-row groups), n = 0..7.
__device__ unsigned g_flag[32][8 * 32];

// -------------------- PTX helpers (sm_80-level only; no 'a' features) ------
__device__ __forceinline__ uint32_t smem_u32(const void* p) {
    uint32_t a;
    asm("{ .reg .u64 t; cvta.to.shared.u64 t, %1; cvt.u32.u64 %0, t; }" : "=r"(a) : "l"(p));
    return a;
}
__device__ __forceinline__ void cp16(uint32_t s, const void* g) {
    asm volatile("cp.async.cg.shared.global [%0], [%1], 16;" :: "r"(s), "l"(g));
}
#define CP_COMMIT() asm volatile("cp.async.commit_group;" ::: "memory")
#define CP_WAIT(n)  asm volatile("cp.async.wait_group %0;" :: "n"(n) : "memory")
#define BARH(id)    asm volatile("bar.sync %0, 128;" :: "r"(id) : "memory")

__device__ __forceinline__ void st_rel_shared(uint32_t addr, unsigned v) {
    asm volatile("st.release.cta.shared.u32 [%0], %1;" :: "r"(addr), "r"(v) : "memory");
}
__device__ __forceinline__ unsigned ld_acq_shared(uint32_t addr) {
    unsigned v;
    asm volatile("ld.acquire.cta.shared.u32 %0, [%1];" : "=r"(v) : "r"(addr) : "memory");
    return v;
}

__device__ __forceinline__ void ldsm4(uint32_t* r, uint32_t addr) {
    asm volatile("ldmatrix.sync.aligned.m8n8.x4.shared.b16 {%0,%1,%2,%3}, [%4];"
                 : "=r"(r[0]), "=r"(r[1]), "=r"(r[2]), "=r"(r[3]) : "r"(addr));
}
__device__ __forceinline__ void mma16816(float* d, const uint32_t* a, uint32_t b0, uint32_t b1) {
    asm volatile("mma.sync.aligned.m16n8k16.row.col.f32.bf16.bf16.f32 "
                 "{%0,%1,%2,%3}, {%4,%5,%6,%7}, {%8,%9}, {%0,%1,%2,%3};"
                 : "+f"(d[0]), "+f"(d[1]), "+f"(d[2]), "+f"(d[3])
                 : "r"(a[0]), "r"(a[1]), "r"(a[2]), "r"(a[3]), "r"(b0), "r"(b1));
}

// fast tanh: 1 - 2/(e^{2x}+1) via MUFU (abs err ~1e-6; saturates correctly)
__device__ __forceinline__ float fast_tanh(float x) {
    float e = __expf(2.0f * x);
    return 1.0f - __fdividef(2.0f, e + 1.0f);
}

// -------------------- split helpers ----------------------------------------
__device__ __forceinline__ void split1(float x, __nv_bfloat16& h, __nv_bfloat16& l) {
    h = __float2bfloat16_rn(x);
    l = __float2bfloat16_rn(x - __bfloat162float(h));
}

__global__ __launch_bounds__(256) void split_kernel(const float* __restrict__ src,
                                                    __nv_bfloat16* __restrict__ hi,
                                                    __nv_bfloat16* __restrict__ lo, int n4) {
    for (int i = blockIdx.x * blockDim.x + threadIdx.x; i < n4; i += gridDim.x * blockDim.x) {
        float4 v = ((const float4*)src)[i];
        __nv_bfloat16 h0, h1, h2, h3, l0, l1, l2, l3;
        split1(v.x, h0, l0); split1(v.y, h1, l1);
        split1(v.z, h2, l2); split1(v.w, h3, l3);
        __nv_bfloat162* ph = (__nv_bfloat162*)hi;
        __nv_bfloat162* pl = (__nv_bfloat162*)lo;
        ph[i * 2] = __nv_bfloat162(h0, h1); ph[i * 2 + 1] = __nv_bfloat162(h2, h3);
        pl[i * 2] = __nv_bfloat162(l0, l1); pl[i * 2 + 1] = __nv_bfloat162(l2, l3);
    }
}

// -------------------- async tile loader (64-col bf16 tiles) ----------------
template <int ROWS, int THREADS>
__device__ __forceinline__ void load_tile_async(const __nv_bfloat16* __restrict__ g,
                                                size_t row0, int kbase,
                                                uint32_t sdst, int tid) {
    constexpr int TOT = ROWS * 8;  // 16B granules
#pragma unroll
    for (int i = 0; i < TOT / THREADS; ++i) {
        int v = i * THREADS + tid;
        int row = v >> 3, g16 = v & 7;
        uint32_t off = (uint32_t)(row * 128 + ((g16 * 16) ^ ((row & 7) * 16)));
        cp16(sdst + off, g + (row0 + (size_t)row) * HH + kbase + g16 * 8);
    }
}

// -------------------- xp GEMM with fused X conversion (round-14 proven) ----
#define FX_SA 8192
#define FX_STAGE 49152
#define FX_SMEM (2 * FX_STAGE)   // 98304

__global__ void __launch_bounds__(256, 2)
xp_gemm_fx(const float* __restrict__ X,
           const __nv_bfloat16* __restrict__ Bhi, const __nv_bfloat16* __restrict__ Blo,
           const float* __restrict__ bih, const float* __restrict__ bhh,
           float* __restrict__ out_f)
{
    extern __shared__ char smem[];
    const uint32_t sbase = smem_u32(smem);
    const int tid = threadIdx.x;
    const int wid = tid >> 5, lane = tid & 31;
    const size_t bm = (size_t)blockIdx.y * 64;
    const int bn = blockIdx.x * 128;
    const int wm = (wid & 1) * 32;          // BM/WM = 2
    const int wn = (wid >> 1) * 32;         // BN/WN = 4

    float acc[2][4][4];
#pragma unroll
    for (int mi = 0; mi < 2; ++mi)
#pragma unroll
        for (int ni = 0; ni < 4; ++ni)
#pragma unroll
            for (int q = 0; q < 4; ++q) acc[mi][ni][q] = 0.0f;

    const int sub = lane >> 3, li = lane & 7;
    const int arow = (sub & 1) * 8 + li;
    const int akb  = (sub >> 1) * 16;
    const int brow = (sub >> 1) * 8 + li;
    const int bkb  = (sub & 1) * 16;
    const uint32_t swx = (uint32_t)(li * 16);

    const int csrow = tid >> 1, chf = tid & 1;
    const int clr = csrow >> 1, cch = csrow & 1;

    auto issue_grp = [&](int c, int s) {
        const uint32_t st = sbase + (uint32_t)(s * FX_STAGE);
        const int kb = c * 64;
#pragma unroll
        for (int i = 0; i < 4; ++i) {
            int gi = i * 256 + tid;          // 1024 granules
            int srow = gi >> 3, gq = gi & 7;
            int lr = srow >> 1, ch = srow & 1;
            uint32_t off = (uint32_t)(srow * 128 + ((gq * 16) ^ ((srow & 7) * 16)));
            cp16(st + off, X + (bm + (size_t)lr) * DD + kb + ch * 32 + gq * 4);
        }
        load_tile_async<128, 256>(Bhi, (size_t)bn, kb, st + 16384, tid);
        load_tile_async<128, 256>(Blo, (size_t)bn, kb, st + 32768, tid);
        CP_COMMIT();
    };

    issue_grp(0, 0);

    for (int c = 0; c < 8; ++c) {
        const int s = c & 1;
        if (c + 1 < 8) {
            issue_grp(c + 1, s ^ 1);
            CP_WAIT(1);
        } else {
            CP_WAIT(0);
        }
        __syncthreads();               // sync1: staging(s) + B(s) visible

        float4 xv[4];
        {
            const char* stg = smem + s * FX_STAGE;
            const uint32_t rb = (uint32_t)(csrow * 128);
            const uint32_t s16 = (uint32_t)((csrow & 7) * 16);
#pragma unroll
            for (int k = 0; k < 4; ++k) {
                uint32_t gq = (uint32_t)(chf * 4 + k);
                xv[k] = *(const float4*)(stg + rb + ((gq * 16) ^ s16));
            }
        }
        __syncthreads();               // sync2: staging reads done

        {
            uint32_t hi[8], lo[8];
#pragma unroll
            for (int k = 0; k < 4; ++k) {
                __nv_bfloat16 h0, l0, h1, l1, h2, l2, h3, l3;
                split1(xv[k].x, h0, l0); split1(xv[k].y, h1, l1);
                split1(xv[k].z, h2, l2); split1(xv[k].w, h3, l3);
                __nv_bfloat162 hp0(h0, h1), hp1(h2, h3), lp0(l0, l1), lp1(l2, l3);
                hi[k * 2] = *(uint32_t*)&hp0; hi[k * 2 + 1] = *(uint32_t*)&hp1;
                lo[k * 2] = *(uint32_t*)&lp0; lo[k * 2 + 1] = *(uint32_t*)&lp1;
            }
            const uint32_t ga = (uint32_t)(cch * 4 + chf * 2);
            const uint32_t s16 = (uint32_t)((clr & 7) * 16);
            const uint32_t off = (uint32_t)(clr * 128) + ((ga * 16) ^ s16);
            const uint32_t off2 = off ^ 16;
            char* stg = smem + s * FX_STAGE;
            *(uint4*)(stg + off)  = make_uint4(hi[0], hi[1], hi[2], hi[3]);
            *(uint4*)(stg + off2) = make_uint4(hi[4], hi[5], hi[6], hi[7]);
            *(uint4*)(stg + FX_SA + off)  = make_uint4(lo[0], lo[1], lo[2], lo[3]);
            *(uint4*)(stg + FX_SA + off2) = make_uint4(lo[4], lo[5], lo[6], lo[7]);
        }
        __syncthreads();               // sync3: A(s) hi/lo ready

        const uint32_t st = sbase + (uint32_t)(s * FX_STAGE);
        const uint32_t aHi = st + (uint32_t)((wm + arow) * 128);
        const uint32_t aLo = aHi + FX_SA;
        const uint32_t bHi = st + 16384 + (uint32_t)((wn + brow) * 128);
        const uint32_t bLo = bHi + 16384;

#pragma unroll
        for (int kk = 0; kk < 4; ++kk) {
            const uint32_t ka = (uint32_t)(kk * 32 + akb) ^ swx;
            const uint32_t kb2 = (uint32_t)(kk * 32 + bkb) ^ swx;
            uint32_t ah[2][4], al[2][4], bh[2][4], bl[2][4];
#pragma unroll
            for (int mi = 0; mi < 2; ++mi) {
                ldsm4(ah[mi], aHi + mi * 2048 + ka);
                ldsm4(al[mi], aLo + mi * 2048 + ka);
            }
#pragma unroll
            for (int nj = 0; nj < 2; ++nj) {
                ldsm4(bh[nj], bHi + nj * 2048 + kb2);
                ldsm4(bl[nj], bLo + nj * 2048 + kb2);
            }
#pragma unroll
            for (int mi = 0; mi < 2; ++mi)
#pragma unroll
                for (int ni = 0; ni < 4; ++ni)
                    mma16816(acc[mi][ni], ah[mi],
                             bh[ni >> 1][2 * (ni & 1)], bh[ni >> 1][2 * (ni & 1) + 1]);
#pragma unroll
            for (int mi = 0; mi < 2; ++mi)
#pragma unroll
                for (int ni = 0; ni < 4; ++ni)
                    mma16816(acc[mi][ni], ah[mi],
                             bl[ni >> 1][2 * (ni & 1)], bl[ni >> 1][2 * (ni & 1) + 1]);
#pragma unroll
            for (int mi = 0; mi < 2; ++mi)
#pragma unroll
                for (int ni = 0; ni < 4; ++ni)
                    mma16816(acc[mi][ni], al[mi],
                             bh[ni >> 1][2 * (ni & 1)], bh[ni >> 1][2 * (ni & 1) + 1]);
        }
        __syncthreads();               // sync4: stage s free
    }

    const int g = lane >> 2, tg = lane & 3;
#pragma unroll
    for (int mi = 0; mi < 2; ++mi) {
#pragma unroll
        for (int ni = 0; ni < 4; ++ni) {
            const size_t r0 = bm + (size_t)(wm + mi * 16 + g);
            const size_t r1 = r0 + 8;
            const int c0 = bn + wn + ni * 8 + 2 * tg;
            float b0 = bih[c0] + bhh[c0];
            float b1 = bih[c0 + 1] + bhh[c0 + 1];
            *(float2*)(out_f + r0 * HH + c0) =
                make_float2(acc[mi][ni][0] + b0, acc[mi][ni][1] + b1);
            *(float2*)(out_f + r1 * HH + c0) =
                make_float2(acc[mi][ni][2] + b0, acc[mi][ni][3] + b1);
        }
    }
}

// -------------------- persistent recurrence kernel -------------------------
// Round-11 structure with two deltas: (1) xp read into registers via LDG at
// step top (no cp group, no smem round trip); (2) finer compute batching:
// chunks computed after wait_group 6/4/2/0 in batches {1},{2,3},{4,5},{6,7}.
#define NCTA 128
#define SMB 0                 // W_hh: hi [0,64K), lo [64K,128K); chunk stride 8K
#define SMB_SPLIT 65536
#define SMB_CHUNK 8192
#define SMA 131072            // A: + half*32768 + chunk*4096 (hi +0, lo +2048)
#define SMA_HALF 32768
#define SMA_CHUNK 4096
#define SMMISC 204800         // [0,8): fb per half; [16,80): sready[2][8]
#define PSMEM 204928

__global__ void __launch_bounds__(256, 1)
rnn_persistent_kernel(const float* __restrict__ xp,
                      const __nv_bfloat16* __restrict__ whh_h,
                      const __nv_bfloat16* __restrict__ whh_l,
                      __nv_bfloat16* __restrict__ hhi_base,
                      __nv_bfloat16* __restrict__ hlo_base,
                      float* __restrict__ out)
{
    extern __shared__ char smem[];
    const uint32_t sb = smem_u32(smem);
    const int tid = threadIdx.x;
    const int half = tid >> 7;
    const int htid = tid & 127;
    const int lane = tid & 31;
    const int gidx = blockIdx.x >> 3;       // 0..15
    const int ntile = blockIdx.x & 7;       // 0..7
    const int rg = gidx + half * 16;        // rowgroup 0..31
    const size_t bm = (size_t)rg * 16;      // global row base (16 rows)
    const int bn = ntile * 64;
    const int wn = (htid >> 5) * 16;        // 4 warps/half, WN=16
    const int barid = 1 + half;

    const uint32_t aOff  = (uint32_t)(SMA + half * SMA_HALF);
    const uint32_t aAddr = sb + aOff;
    const uint32_t selfOff = aOff + (uint32_t)(ntile * SMA_CHUNK);
    const uint32_t srBase  = sb + (uint32_t)(SMMISC + 16 + half * 32);

    if (htid == 0) {
        unsigned fb0;
        asm volatile("ld.volatile.global.u32 %0, [%1];"
                     : "=r"(fb0) : "l"(&g_flag[rg][ntile * 32]));
        *(unsigned*)(smem + SMMISC + half * 4) = fb0;
    }
    if (tid < 16) *(unsigned*)(smem + SMMISC + 16 + tid * 4) = 0;

    // resident W_hh tiles (rows bn..bn+64, all K), both splits (full CTA)
#pragma unroll
    for (int i = 0; i < 32; ++i) {
        int v = i * 256 + tid;
        int split = v >> 12;
        int rem = v & 4095;
        int chunk = rem >> 9;
        int rr = rem & 511;
        int row = rr >> 3, gq = rr & 7;
        const __nv_bfloat16* src = (split ? whh_l : whh_h);
        uint32_t dst = sb + SMB + split * SMB_SPLIT + chunk * SMB_CHUNK
                     + row * 128 + (uint32_t)((gq * 16) ^ ((row & 7) * 16));
        cp16(dst, src + (size_t)(bn + row) * HH + chunk * 64 + gq * 8);
    }
    CP_COMMIT();

    auto sts4 = [&](uint32_t base, int row, int lc, uint32_t val) {
        uint32_t bc = (uint32_t)(lc * 2);
        uint32_t off = (uint32_t)(row * 128)
                     + ((bc & ~15u) ^ (((uint32_t)(row & 7)) << 4)) + (bc & 15u);
        *(uint32_t*)(smem + base + off) = val;
    };

    // step 0: h1 = tanh(xp_0) -> buf 0 + self smem chunk
#pragma unroll
    for (int i = 0; i < 2; ++i) {
        int v = i * 128 + htid;
        int row = v >> 4, c4 = v & 15;
        const float4 x = *(const float4*)(xp + (bm + row) * HH + bn + c4 * 4);
        float v0 = fast_tanh(x.x), v1 = fast_tanh(x.y);
        float v2 = fast_tanh(x.z), v3 = fast_tanh(x.w);
        __nv_bfloat16 h0, l0, h1, l1, h2, l2, h3, l3;
        split1(v0, h0, l0); split1(v1, h1, l1);
        split1(v2, h2, l2); split1(v3, h3, l3);
        __nv_bfloat162 hp0(h0, h1), hp1(h2, h3), lp0(l0, l1), lp1(l2, l3);
        size_t off = (bm + row) * HH + bn + c4 * 4;
        *(uint2*)(hhi_base + off) = make_uint2(*(uint32_t*)&hp0, *(uint32_t*)&hp1);
        *(uint2*)(hlo_base + off) = make_uint2(*(uint32_t*)&lp0, *(uint32_t*)&lp1);
        sts4(selfOff, row, c4 * 4, *(uint32_t*)&hp0);
        sts4(selfOff, row, c4 * 4 + 2, *(uint32_t*)&hp1);
        sts4(selfOff + 2048, row, c4 * 4, *(uint32_t*)&lp0);
        sts4(selfOff + 2048, row, c4 * 4 + 2, *(uint32_t*)&lp1);
    }
    CP_WAIT(0);
    __syncthreads();
    const unsigned fb = *(const unsigned*)(smem + SMMISC + half * 4);
    if (htid == 0)
        asm volatile("red.release.gpu.global.add.u32 [%0], %1;"
                     :: "l"(&g_flag[rg][ntile * 32]), "r"(1u) : "memory");

    const int sub = lane >> 3, li = lane & 7;
    const int arow = (sub & 1) * 8 + li;
    const int akb  = (sub >> 1) * 16;
    const int brow = (sub >> 1) * 8 + li;
    const int bkb  = (sub & 1) * 16;
    const uint32_t swx = (uint32_t)(li * 16);
    const int gl = lane >> 2, tg = lane & 3;

    for (int t = 1; t < TT; ++t) {
        const __nv_bfloat16* Ah = hhi_base + (size_t)((t - 1) & 1) * BH;
        const __nv_bfloat16* Al = hlo_base + (size_t)((t - 1) & 1) * BH;
        __nv_bfloat16* Oh = hhi_base + (size_t)(t & 1) * BH;
        __nv_bfloat16* Ol = hlo_base + (size_t)(t & 1) * BH;
        const float* xpt = xp + (size_t)t * BH;

        float acc[2][4];
#pragma unroll
        for (int ni = 0; ni < 2; ++ni)
#pragma unroll
            for (int q = 0; q < 4; ++q) acc[ni][q] = 0.0f;

        // phase -1: xp for this thread's epilogue -> registers (LDG, covered
        // by ~1.7us of compute before use)
        float2 xr[4];
#pragma unroll
        for (int ni = 0; ni < 2; ++ni) {
            const int lc = wn + ni * 8 + 2 * tg;
            xr[ni * 2]     = *(const float2*)(xpt + (bm + (size_t)gl) * HH + bn + lc);
            xr[ni * 2 + 1] = *(const float2*)(xpt + (bm + (size_t)(gl + 8)) * HH + bn + lc);
        }

        auto compute_chunk = [&](int c) {
            const uint32_t aHi = aAddr + c * SMA_CHUNK + (uint32_t)(arow * 128);
            const uint32_t aLo = aHi + 2048;
            const uint32_t bHi = sb + SMB + c * SMB_CHUNK + (uint32_t)((wn + brow) * 128);
            const uint32_t bLo = bHi + SMB_SPLIT;
#pragma unroll
            for (int kk = 0; kk < 4; ++kk) {
                const uint32_t ka  = (uint32_t)(kk * 32 + akb) ^ swx;
                const uint32_t kb2 = (uint32_t)(kk * 32 + bkb) ^ swx;
                uint32_t ah[4], al4[4], bh[4], bl[4];
                ldsm4(ah, aHi + ka);
                ldsm4(al4, aLo + ka);
                ldsm4(bh, bHi + kb2);
                ldsm4(bl, bLo + kb2);
#pragma unroll
                for (int ni = 0; ni < 2; ++ni)
                    mma16816(acc[ni], ah, bh[2 * ni], bh[2 * ni + 1]);
#pragma unroll
                for (int ni = 0; ni < 2; ++ni)
                    mma16816(acc[ni], ah, bl[2 * ni], bl[2 * ni + 1]);
#pragma unroll
                for (int ni = 0; ni < 2; ++ni)
                    mma16816(acc[ni], al4, bh[2 * ni], bh[2 * ni + 1]);
            }
        };

        // phase 0: self chunk (A in smem from own previous epilogue)
        compute_chunk(ntile);

        // phase 1: eager poll + publish (threads 0..6)
        if (htid < 7) {
            const int c = (ntile + 1 + htid) & 7;
            const unsigned* fl = &g_flag[rg][c * 32];
            const unsigned target = fb + (unsigned)t;
            unsigned v;
            do {
                asm volatile("ld.acquire.gpu.global.u32 %0, [%1];" : "=r"(v) : "l"(fl));
            } while ((int)(v - target) < 0);
            st_rel_shared(srBase + (uint32_t)((htid + 1) * 4), (unsigned)t);
        }

        // phase 2: eager per-chunk issue (7 groups, chunks j=1..7)
#pragma unroll
        for (int j = 1; j < 8; ++j) {
            const uint32_t sr = srBase + (uint32_t)(j * 4);
            while ((int)(ld_acq_shared(sr) - (unsigned)t) < 0) { }
            const int c = (ntile + j) & 7;
            const uint32_t base = aAddr + c * SMA_CHUNK;
#pragma unroll
            for (int i = 0; i < 2; ++i) {
                int v = i * 128 + htid;
                int split = v >> 7;
                int rr = v & 127;
                int row = rr >> 3, gq = rr & 7;
                const __nv_bfloat16* src = (split ? Al : Ah);
                uint32_t dst = base + split * 2048 + row * 128
                             + (uint32_t)((gq * 16) ^ ((row & 7) * 16));
                cp16(dst, src + (bm + (size_t)row) * HH + c * 64 + gq * 8);
            }
            CP_COMMIT();
        }

        // phase 3: fine-grained batched waits + computes
        CP_WAIT(6);                       // chunk 1 landed
        BARH(barid);
        compute_chunk((ntile + 1) & 7);
        CP_WAIT(4);                       // chunks 2,3
        BARH(barid);
        compute_chunk((ntile + 2) & 7);
        compute_chunk((ntile + 3) & 7);
        CP_WAIT(2);                       // chunks 4,5
        BARH(barid);
        compute_chunk((ntile + 4) & 7);
        compute_chunk((ntile + 5) & 7);
        CP_WAIT(0);                       // chunks 6,7
        BARH(barid);
        compute_chunk((ntile + 6) & 7);
        compute_chunk((ntile + 7) & 7);

        // phase 4: epilogue — tanh(acc + xp_regs); write h (or final out)
#pragma unroll
        for (int ni = 0; ni < 2; ++ni) {
            const int lr0 = gl;
            const int lc  = wn + ni * 8 + 2 * tg;
            const size_t r0 = bm + (size_t)lr0;
            const size_t r1 = r0 + 8;
            const int c0 = bn + lc;
            float2 x0 = xr[ni * 2];
            float2 x1 = xr[ni * 2 + 1];
            float v0 = fast_tanh(acc[ni][0] + x0.x);
            float v1 = fast_tanh(acc[ni][1] + x0.y);
            float v2 = fast_tanh(acc[ni][2] + x1.x);
            float v3 = fast_tanh(acc[ni][3] + x1.y);
            if (t == TT - 1) {
                *(float2*)(out + r0 * HH + c0) = make_float2(v0, v1);
                *(float2*)(out + r1 * HH + c0) = make_float2(v2, v3);
            } else {
                __nv_bfloat16 h0, l0, h1, l1, h2, l2, h3, l3;
                split1(v0, h0, l0); split1(v1, h1, l1);
                split1(v2, h2, l2); split1(v3, h3, l3);
                __nv_bfloat162 hp0(h0, h1), hp1(h2, h3), lp0(l0, l1), lp1(l2, l3);
                *(uint32_t*)(Oh + r0 * HH + c0) = *(uint32_t*)&hp0;
                *(uint32_t*)(Ol + r0 * HH + c0) = *(uint32_t*)&lp0;
                *(uint32_t*)(Oh + r1 * HH + c0) = *(uint32_t*)&hp1;
                *(uint32_t*)(Ol + r1 * HH + c0) = *(uint32_t*)&lp1;
                sts4(selfOff, lr0, lc, *(uint32_t*)&hp0);
                sts4(selfOff + 2048, lr0, lc, *(uint32_t*)&lp0);
                sts4(selfOff, lr0 + 8, lc, *(uint32_t*)&hp1);
                sts4(selfOff + 2048, lr0 + 8, lc, *(uint32_t*)&lp1);
            }
        }

        BARH(barid);
        if (htid == 0 && t < TT - 1)
            asm volatile("red.release.gpu.global.add.u32 [%0], %1;"
                         :: "l"(&g_flag[rg][ntile * 32]), "r"(1u) : "memory");
    }
}

// -------------------- launcher ---------------------------------------------
extern "C" void kernel_launch(void* const* d_in, const int* in_sizes, int n_in,
                              void* d_out, int out_size)
{
    const float* X   = (const float*)d_in[0];
    const float* Wih = (const float*)d_in[1];
    const float* Whh = (const float*)d_in[2];
    const float* bih = (const float*)d_in[3];
    const float* bhh = (const float*)d_in[4];
    float* out = (float*)d_out;

    float* xp;
    __nv_bfloat16 *wih_h, *wih_l, *whh_h, *whh_l, *hhi, *hlo;
    cudaGetSymbolAddress((void**)&xp, g_xp);
    cudaGetSymbolAddress((void**)&wih_h, g_wih_h);
    cudaGetSymbolAddress((void**)&wih_l, g_wih_l);
    cudaGetSymbolAddress((void**)&whh_h, g_whh_h);
    cudaGetSymbolAddress((void**)&whh_l, g_whh_l);
    cudaGetSymbolAddress((void**)&hhi, g_hhi);
    cudaGetSymbolAddress((void**)&hlo, g_hlo);

    cudaFuncSetAttribute(xp_gemm_fx,
                         cudaFuncAttributeMaxDynamicSharedMemorySize, FX_SMEM);
    cudaFuncSetAttribute(rnn_persistent_kernel,
                         cudaFuncAttributeMaxDynamicSharedMemorySize, PSMEM);

    // 1) hi/lo splits of weights only (X conversion fused into xp GEMM)
    split_kernel<<<128, 256>>>(Wih, wih_h, wih_l, HH * DD / 4);
    split_kernel<<<128, 256>>>(Whh, whh_h, whh_l, HH * HH / 4);

    // 2) xp = X @ Wih^T + (b_ih + b_hh), fused fp32 conversion
    {
        dim3 g(HH / 128, (TT * BB) / 64);  // (4, 4096)
        xp_gemm_fx<<<g, 256, FX_SMEM>>>(X, wih_h, wih_l, bih, bhh, xp);
    }

    // 3) entire recurrence in one persistent kernel
    rnn_persistent_kernel<<<NCTA, 256, PSMEM>>>(xp, whh_h, whh_l, hhi, hlo, out);
}